// round 10
// baseline (speedup 1.0000x reference)
#include <cuda_runtime.h>
#include <math.h>

#define NPTS    200000
#define NBINS   512
#define TPB     128
#define BLOCKS  ((NPTS + TPB - 1) / TPB)   // 1563, one point per thread
#define WPB     4                          // warps per block
#define NCOPY   32                         // global hist copies

// Global accumulators + completion ticket. Invariant: all zero at launch
// start; the last block restores them after writing d_out (graph-replay safe).
__device__ float        g_hist[NCOPY][NBINS];
__device__ unsigned int g_ticket;

__device__ __forceinline__ float ex2f(float x) {
    float y;
    asm("ex2.approx.f32 %0, %1;" : "=f"(y) : "f"(x));
    return y;
}
__device__ __forceinline__ float ldcg(const float* p) {
    float v;
    asm volatile("ld.global.cg.f32 %0, [%1];" : "=f"(v) : "l"(p));
    return v;
}

// ---------------------------------------------------------------------------
// Single fused kernel. pdf = e*(A + B(r-r0)), B>0 => clip-at-0 is exactly
// r >= r0 - A/B; window = [r0 - min(3.75sig, A/B), r0 + 3.75sig] (~42 bins).
// Block-wide compaction + round-robin warps + software-pipelined scatter.
// ---------------------------------------------------------------------------
__global__ void __launch_bounds__(TPB, 12) main_kernel(
        const float* __restrict__ means,
        const float* __restrict__ scan_point,
        const float* __restrict__ colours,
        const float* __restrict__ coefficients,
        const float* __restrict__ opacities,
        const float* __restrict__ scales,
        float* __restrict__ out)
{
    __shared__ float  hist[WPB][NBINS];   // 8 KB: per-warp private hist
    __shared__ float4 cp[TPB];            // 2 KB: compacted (k, mneg, B, A2)
    __shared__ float4 cq[TPB];            // 2 KB: compacted (I, rt0, pk, -)
    __shared__ int    s_cnt;
    __shared__ unsigned int s_last;

    const int   tid   = threadIdx.x;
    const int   w     = tid >> 5;
    const int   lane  = tid & 31;
    const float flane = 0.005f * (float)lane;

    // zero own warp's hist; init counter
    #pragma unroll
    for (int t = 0; t < NBINS / 32; ++t) hist[w][lane + 32 * t] = 0.0f;
    if (tid == 0) s_cnt = 0;
    __syncthreads();

    // ---- fold phase: one point per thread ----
    const int p = blockIdx.x * TPB + tid;
    float4 P = make_float4(0.f, 0.f, 0.f, 0.f);
    float  I = 0.f, rt0 = 0.f;
    int    pk = 0;
    if (p < NPTS) {
        float sx = scan_point[0], sy = scan_point[1], sz = scan_point[2];
        float dx = means[3 * p + 0] - sx;
        float dy = means[3 * p + 1] - sy;
        float dz = means[3 * p + 2] - sz;
        float r0 = sqrtf(fmaf(dx, dx, fmaf(dy, dy, dz * dz)));

        float sigma = fmaxf(__expf(scales[p]), 0.005f);   // BIN_RES/2
        float sinv  = __frcp_rn(sigma);

        float coeff = __frcp_rn(1.0f + __expf(-coefficients[p]));

        float op = opacities[p];
        float co = colours[p];
        I = (op * op) * (co * co);

        // pdf*(h/2) = e * (A + B*(r-r0));  gg = fma(r, B, A2)
        float A  = 0.005f * 0.3989422804014327f * coeff * sinv;
        float B  = 0.005f * (1.0f - coeff) * sinv * sinv;
        float A2 = A - B * r0;

        // e = 2^(-(d*k)^2), k = sinv*sqrt(0.5*log2 e)
        float k    = 0.84932180028802f * sinv;
        float mneg = -r0 * k;
        P = make_float4(k, mneg, B, A2);

        // window: left = clip zero-crossing (exact), right = 3.75 sigma
        float W   = 3.18496f / k;             // 3.75 sigma in r units
        float AoB = A * __frcp_rn(B);         // ~0.4 sigma
        float lo  = r0 - fminf(W, AoB);
        float hi  = r0 + W;
        int b0 = max(0,   (int)ceilf (lo * 200.0f - 1.0f));
        int b1 = min(511, (int)floorf(hi * 200.0f - 1.0f));
        int nb = max(0, b1 - b0 + 1);
        pk  = b0 | (nb << 16);
        rt0 = 0.005f * (float)(b0 + 1);
    }

    // ---- block-wide compaction (warp-aggregated shared atomics) ----
    bool     act = (pk >> 16) != 0;
    unsigned m   = __ballot_sync(0xFFFFFFFFu, act);
    int base = 0;
    if (lane == 0 && m) base = atomicAdd(&s_cnt, __popc(m));
    base = __shfl_sync(0xFFFFFFFFu, base, 0);
    if (act) {
        int pos = base + __popc(m & ((1u << lane) - 1u));
        cp[pos] = P;
        cq[pos] = make_float4(I, rt0, __int_as_float(pk), 0.f);
    }
    __syncthreads();
    const int cnt = s_cnt;

    // ---- scatter: warps round-robin, software-pipelined point prefetch ----
    float4 iq, q;
    int j = w;
    if (j < cnt) { iq = cq[j]; q = cp[j]; }
    while (j < cnt) {
        const int jn = j + WPB;
        float4 iq_n, q_n;
        if (jn < cnt) { iq_n = cq[jn]; q_n = cp[jn]; }   // prefetch next point

        int pkj = __float_as_int(iq.z);
        int nb  = pkj >> 16;
        int   b   = (pkj & 0xFFFF) + lane;
        float Ij  = iq.x;
        float rt  = iq.y + flane;

        // step 0: bins [b0, b0+32)
        {
            float u  = fmaf(rt, q.x, q.y);
            float e  = ex2f(-u * u);
            float gg = fmaf(rt, q.z, q.w);
            float pr = __saturatef(e * gg);
            if (lane < nb)
                hist[w][b] = fmaf(Ij, pr, hist[w][b]);
        }
        // step 1: bins [b0+32, b0+64)  (warp-uniform guard)
        if (nb > 32) {
            float rt1 = rt + 0.16f;
            float u  = fmaf(rt1, q.x, q.y);
            float e  = ex2f(-u * u);
            float gg = fmaf(rt1, q.z, q.w);
            float pr = __saturatef(e * gg);
            if (lane + 32 < nb)
                hist[w][b + 32] = fmaf(Ij, pr, hist[w][b + 32]);
        }
        // rare tail: nb > 64
        if (nb > 64) {
            float rts = rt + 0.32f;
            int   bs  = b + 64;
            for (int done = 64; done < nb; done += 32) {
                float u  = fmaf(rts, q.x, q.y);
                float e  = ex2f(-u * u);
                float gg = fmaf(rts, q.z, q.w);
                float pr = __saturatef(e * gg);
                if (done + lane < nb)
                    hist[w][bs] = fmaf(Ij, pr, hist[w][bs]);
                rts += 0.16f;
                bs  += 32;
            }
        }

        iq = iq_n; q = q_n; j = jn;
    }

    // ---- merge 4 warp hists -> one of 32 global copies ----
    __syncthreads();
    float* __restrict__ gh = g_hist[blockIdx.x & (NCOPY - 1)];
    #pragma unroll
    for (int b = tid; b < NBINS; b += TPB) {
        float s = 0.0f;
        #pragma unroll
        for (int ww = 0; ww < WPB; ++ww) s += hist[ww][b];
        atomicAdd(&gh[b], s);
    }

    // ---- last-block finalize (no spinning: only the final arrival acts) ----
    __threadfence();
    if (tid == 0)
        s_last = atomicAdd(&g_ticket, 1u);
    __syncthreads();

    if (s_last == BLOCKS - 1) {
        __threadfence();
        #pragma unroll
        for (int b = tid; b < NBINS; b += TPB) {
            float v = 0.0f;
            #pragma unroll
            for (int c = 0; c < NCOPY; ++c) {
                v += ldcg(&g_hist[c][b]);
                g_hist[c][b] = 0.0f;              // restore invariant
            }
            float r = 0.005f * (float)(b + 1);
            out[b] = v / (r * r);
        }
        __threadfence();
        __syncthreads();
        if (tid == 0) g_ticket = 0u;              // restore invariant
    }
}

// ---------------------------------------------------------------------------
extern "C" void kernel_launch(void* const* d_in, const int* in_sizes, int n_in,
                              void* d_out, int out_size)
{
    const float* means        = (const float*)d_in[0];
    const float* scan_point   = (const float*)d_in[1];
    const float* colours      = (const float*)d_in[2];
    const float* coefficients = (const float*)d_in[3];
    const float* opacities    = (const float*)d_in[4];
    const float* scales       = (const float*)d_in[5];

    float* out = (float*)d_out;

    main_kernel<<<BLOCKS, TPB>>>(means, scan_point, colours,
                                 coefficients, opacities, scales, out);
}

// round 11
// speedup vs baseline: 1.1373x; 1.1373x over previous
#include <cuda_runtime.h>
#include <math.h>

#define NPTS    200000
#define NBINS   512
#define TPB     256
#define BLOCKS  ((NPTS + TPB - 1) / TPB)   // 782, one point per thread
#define WPB     8                          // warps per block
#define HPAD    640                        // padded hist row (b0+63 <= 574)
#define NCOPY   32                         // global hist copies

// Global accumulators + completion ticket. Invariant: all zero at launch
// start; the last block restores them after writing d_out (graph-replay safe).
__device__ float        g_hist[NCOPY][NBINS];
__device__ unsigned int g_ticket;

__device__ __forceinline__ float ex2f(float x) {
    float y;
    asm("ex2.approx.f32 %0, %1;" : "=f"(y) : "f"(x));
    return y;
}
__device__ __forceinline__ float ldcg(const float* p) {
    float v;
    asm volatile("ld.global.cg.f32 %0, [%1];" : "=f"(v) : "l"(p));
    return v;
}

// ---------------------------------------------------------------------------
// Single fused kernel, BRANCHLESS inner loop:
//  - left clip handled exactly by __saturatef (pdf<0 -> 0)
//  - right tail beyond 3.75 sigma: tiny positive, reference includes it too
//  - every point does exactly 64 bins [b0, b0+64); hist rows padded to 640
//    so out-of-range bins land in a discard pad. No BSSY/BSYNC in hot loop.
// ---------------------------------------------------------------------------
__global__ void __launch_bounds__(TPB, 6) main_kernel(
        const float* __restrict__ means,
        const float* __restrict__ scan_point,
        const float* __restrict__ colours,
        const float* __restrict__ coefficients,
        const float* __restrict__ opacities,
        const float* __restrict__ scales,
        float* __restrict__ out)
{
    __shared__ float  hist[WPB][HPAD];    // 20 KB: per-warp hist + pad
    __shared__ float4 cp[TPB];            //  4 KB: compacted (k, mneg, B, A2)
    __shared__ float4 cq[TPB];            //  4 KB: compacted (I, rt0, b0, -)
    __shared__ int    s_cnt;
    __shared__ unsigned int s_last;

    const int   tid   = threadIdx.x;
    const int   w     = tid >> 5;
    const int   lane  = tid & 31;
    const float flane = 0.005f * (float)lane;

    // zero own warp's hist (incl. pad); init counter
    #pragma unroll
    for (int t = 0; t < HPAD / 32; ++t) hist[w][lane + 32 * t] = 0.0f;
    if (tid == 0) s_cnt = 0;
    __syncthreads();

    // ---- fold phase: one point per thread ----
    const int p = blockIdx.x * TPB + tid;
    float4 P = make_float4(0.f, 0.f, 0.f, 0.f);
    float  I = 0.f, rt0 = 0.f;
    int    b0 = 0;
    bool   act = false;
    if (p < NPTS) {
        float sx = scan_point[0], sy = scan_point[1], sz = scan_point[2];
        float dx = means[3 * p + 0] - sx;
        float dy = means[3 * p + 1] - sy;
        float dz = means[3 * p + 2] - sz;
        float r0 = sqrtf(fmaf(dx, dx, fmaf(dy, dy, dz * dz)));

        float sigma = fmaxf(__expf(scales[p]), 0.005f);   // BIN_RES/2
        float sinv  = __frcp_rn(sigma);

        float coeff = __frcp_rn(1.0f + __expf(-coefficients[p]));

        float op = opacities[p];
        float co = colours[p];
        I = (op * op) * (co * co);

        // pdf*(h/2) = e * (A + B*(r-r0));  gg = fma(r, B, A2)
        float A  = 0.005f * 0.3989422804014327f * coeff * sinv;
        float B  = 0.005f * (1.0f - coeff) * sinv * sinv;
        float A2 = A - B * r0;

        // e = 2^(-(d*k)^2), k = sinv*sqrt(0.5*log2 e)
        float k    = 0.84932180028802f * sinv;
        float mneg = -r0 * k;
        P = make_float4(k, mneg, B, A2);

        // window start: left = clip zero-crossing r0 - A/B (exact bound),
        // capped by 3.75 sigma; 64 bins from b0 cover the support.
        float W   = 3.18496f / k;             // 3.75 sigma in r units
        float AoB = A * __frcp_rn(B);         // ~0.4 sigma
        float lo  = r0 - fminf(W, AoB);
        float hi  = r0 + W;
        b0  = max(0, (int)ceilf(lo * 200.0f - 1.0f));
        act = (b0 <= 511) && (hi > 0.0f);
        rt0 = 0.005f * (float)(b0 + 1);
    }

    // ---- block-wide compaction (warp-aggregated shared atomics) ----
    unsigned m = __ballot_sync(0xFFFFFFFFu, act);
    int base = 0;
    if (lane == 0 && m) base = atomicAdd(&s_cnt, __popc(m));
    base = __shfl_sync(0xFFFFFFFFu, base, 0);
    if (act) {
        int pos = base + __popc(m & ((1u << lane) - 1u));
        cp[pos] = P;
        cq[pos] = make_float4(I, rt0, __int_as_float(b0), 0.f);
    }
    __syncthreads();
    const int cnt = s_cnt;

    // ---- scatter: branchless 64-bin sweep per point ----
    #pragma unroll 2
    for (int j = w; j < cnt; j += WPB) {
        float4 iq = cq[j];
        float4 q  = cp[j];
        int   b   = __float_as_int(iq.z) + lane;
        float Ij  = iq.x;
        float rt  = iq.y + flane;

        float u0  = fmaf(rt, q.x, q.y);
        float e0  = ex2f(u0 * -u0);
        float g0  = fmaf(rt, q.z, q.w);
        float p0  = __saturatef(e0 * g0);

        float rt1 = rt + 0.16f;
        float u1  = fmaf(rt1, q.x, q.y);
        float e1  = ex2f(u1 * -u1);
        float g1  = fmaf(rt1, q.z, q.w);
        float p1  = __saturatef(e1 * g1);

        hist[w][b]      = fmaf(Ij, p0, hist[w][b]);
        hist[w][b + 32] = fmaf(Ij, p1, hist[w][b + 32]);
    }

    // ---- merge 8 warp hists -> one of 32 global copies (pad discarded) ----
    __syncthreads();
    float* __restrict__ gh = g_hist[blockIdx.x & (NCOPY - 1)];
    #pragma unroll
    for (int b = tid; b < NBINS; b += TPB) {
        float s = 0.0f;
        #pragma unroll
        for (int ww = 0; ww < WPB; ++ww) s += hist[ww][b];
        atomicAdd(&gh[b], s);
    }

    // ---- last-block finalize (no spinning: only the final arrival acts) ----
    __threadfence();
    if (tid == 0)
        s_last = atomicAdd(&g_ticket, 1u);
    __syncthreads();

    if (s_last == BLOCKS - 1) {
        __threadfence();
        #pragma unroll
        for (int b = tid; b < NBINS; b += TPB) {
            float v = 0.0f;
            #pragma unroll
            for (int c = 0; c < NCOPY; ++c) {
                v += ldcg(&g_hist[c][b]);
                g_hist[c][b] = 0.0f;              // restore invariant
            }
            float r = 0.005f * (float)(b + 1);
            out[b] = v / (r * r);
        }
        __threadfence();
        __syncthreads();
        if (tid == 0) g_ticket = 0u;              // restore invariant
    }
}

// ---------------------------------------------------------------------------
extern "C" void kernel_launch(void* const* d_in, const int* in_sizes, int n_in,
                              void* d_out, int out_size)
{
    const float* means        = (const float*)d_in[0];
    const float* scan_point   = (const float*)d_in[1];
    const float* colours      = (const float*)d_in[2];
    const float* coefficients = (const float*)d_in[3];
    const float* opacities    = (const float*)d_in[4];
    const float* scales       = (const float*)d_in[5];

    float* out = (float*)d_out;

    main_kernel<<<BLOCKS, TPB>>>(means, scan_point, colours,
                                 coefficients, opacities, scales, out);
}